// round 13
// baseline (speedup 1.0000x reference)
#include <cuda_runtime.h>
#include <cuda_bf16.h>
#include <math.h>

#define T  8192
#define E  20
#define H1 30
#define H2 50
#define HL 300
#define NT 50
#define G1 (4*H1)   // 120
#define G2 (4*H2)   // 200
#define D2 (2*H1)   // 60
#define D3 (2*H2)   // 100

// ---- scratch (no allocations allowed) ----
// gx1 & gx2 layout: [t][u][4] with gates in PyTorch order (i,f,g,o)
__device__ float g_gx_fw1[T*G1];
__device__ float g_gx_bw1[T*G1];
__device__ float g_l1[T*D2];
__device__ float g_gx_fw2[T*G2];
__device__ float g_gx_bw2[T*G2];
__device__ float g_l2[T*D3];

typedef unsigned long long u64;

__device__ __forceinline__ u64 pk(float lo, float hi) {
    u64 r; asm("mov.b64 %0, {%1, %2};" : "=l"(r) : "f"(lo), "f"(hi)); return r;
}
__device__ __forceinline__ void upk(u64 v, float& lo, float& hi) {
    asm("mov.b64 {%0, %1}, %2;" : "=f"(lo), "=f"(hi) : "l"(v));
}
__device__ __forceinline__ u64 ffma2(u64 a, u64 b, u64 c) {
    u64 d; asm("fma.rn.f32x2 %0, %1, %2, %3;" : "=l"(d) : "l"(a), "l"(b), "l"(c)); return d;
}
__device__ __forceinline__ u64 addx2(u64 a, u64 b) {
    u64 d; asm("add.rn.f32x2 %0, %1, %2;" : "=l"(d) : "l"(a), "l"(b)); return d;
}
__device__ __forceinline__ float tanh_ap(float x) {
    float y; asm("tanh.approx.f32 %0, %1;" : "=f"(y) : "f"(x)); return y;
}
__device__ __forceinline__ float sig_ap(float x) {
    return fmaf(0.5f, tanh_ap(0.5f*x), 0.5f);
}

// ============================================================
// Kernel 1: embedding gather + layer-1 input projections.
// Writes [t][u][4] (PyTorch gate order within nibble).
// ============================================================
__global__ void k_gx1(const int* __restrict__ x, const float* __restrict__ emb,
                      const float* __restrict__ WihF, const float* __restrict__ bF,
                      const float* __restrict__ WihB, const float* __restrict__ bB) {
    __shared__ float e[E];
    int t = blockIdx.x;
    int j = threadIdx.x;
    if (j < E) e[j] = emb[(size_t)x[t] * E + j];
    __syncthreads();
    if (j < G1) {
        int gi = j / H1, u = j % H1;
        float aF = bF[j], aB = bB[j];
        #pragma unroll
        for (int k = 0; k < E; k++) {
            float ev = e[k];
            aF += WihF[j*E + k] * ev;
            aB += WihB[j*E + k] * ev;
        }
        int dpos = u*4 + gi;
        g_gx_fw1[t*G1 + dpos] = aF;
        g_gx_bw1[(T-1-t)*G1 + dpos] = aB;
    }
}

// ============================================================
// Kernel 2: layer-1 scan — all-4-gates-per-thread, K-half split.
// 64 threads: tid = u*2 + kh (u<30). Per thread: 4 LDS.128
// (K-half of h), 4 half-dots, 4 shfl_xor(1), local gate math,
// redundant c/h update. LDS.128/step per warp: 4 (was 8).
// ============================================================
__global__ void __launch_bounds__(64, 1) k_scan1(
    const float* __restrict__ WhhF, const float* __restrict__ h0F, const float* __restrict__ c0F,
    const float* __restrict__ WhhB, const float* __restrict__ h0B, const float* __restrict__ c0B) {
    const bool bw = (blockIdx.x == 1);
    const float* Whh = bw ? WhhB : WhhF;
    const float* h0  = bw ? h0B  : h0F;
    const float* c0  = bw ? c0B  : c0F;
    const float* gx  = bw ? g_gx_bw1 : g_gx_fw1;
    const int off = bw ? H1 : 0;

    __shared__ __align__(16) float h_sh[2][32];   // 8 ulonglong2 rows; [30..32)=0

    const int tid = threadIdx.x;
    const int u  = tid >> 1;
    const int kh = tid & 1;
    const bool valid = (u < H1);
    const int uu = valid ? u : 0;
    const int khb = kh * 4;                        // ulonglong2 base within h row

    // Weights: 4 gate rows (i,f,g,o), this thread's K-half (16 padded elements).
    u64 wI[8], wF[8], wG[8], wO[8];
    #pragma unroll
    for (int kk = 0; kk < 4; kk++) {
        int base = (khb + kk) * 4;
        #pragma unroll
        for (int g = 0; g < 4; g++) {
            const float* rw = Whh + (g*H1 + uu)*H1;
            float e0 = (valid && base+0 < H1) ? rw[base+0] : 0.f;
            float e1 = (valid && base+1 < H1) ? rw[base+1] : 0.f;
            float e2 = (valid && base+2 < H1) ? rw[base+2] : 0.f;
            float e3 = (valid && base+3 < H1) ? rw[base+3] : 0.f;
            u64 lo = pk(e0, e1), hi = pk(e2, e3);
            if (g == 0) { wI[2*kk] = lo; wI[2*kk+1] = hi; }
            else if (g == 1) { wF[2*kk] = lo; wF[2*kk+1] = hi; }
            else if (g == 2) { wG[2*kk] = lo; wG[2*kk+1] = hi; }
            else { wO[2*kk] = lo; wO[2*kk+1] = hi; }
        }
    }
    const u64 Z = pk(0.f, 0.f);

    if (tid < 32) {
        h_sh[0][tid] = (tid < H1) ? h0[tid] : 0.f;
        h_sh[1][tid] = 0.f;
    }
    float c = valid ? c0[uu] : 0.f;

    // gx: [t][u][4]; kh==0 lane loads one float4 per step (2-deep prefetch)
    const bool gl = valid && (kh == 0);
    const float4* gx4 = (const float4*)gx;
    float4 ga = gl ? gx4[uu]      : make_float4(0.f,0.f,0.f,0.f);
    float4 gb = gl ? gx4[H1 + uu] : make_float4(0.f,0.f,0.f,0.f);
    const float4* pre = gx4 + 2*H1 + uu;
    float* outp = g_l1 + off + uu;
    __syncthreads();

    #define S1_STEP(HR, HW, GV, PF) do {                                        \
        const ulonglong2* _h8 = ((const ulonglong2*)(HR)) + khb;                \
        u64 _iA = pk((GV).x, 0.f), _iB = Z;                                     \
        u64 _fA = pk((GV).y, 0.f), _fB = Z;                                     \
        u64 _gA = pk((GV).z, 0.f), _gB = Z;                                     \
        u64 _oA = pk((GV).w, 0.f), _oB = Z;                                     \
        _Pragma("unroll")                                                       \
        for (int _kk = 0; _kk < 4; _kk++) {                                     \
            ulonglong2 _hv = _h8[_kk];                                          \
            _iA = ffma2(wI[2*_kk],   _hv.x, _iA);                               \
            _iB = ffma2(wI[2*_kk+1], _hv.y, _iB);                               \
            _fA = ffma2(wF[2*_kk],   _hv.x, _fA);                               \
            _fB = ffma2(wF[2*_kk+1], _hv.y, _fB);                               \
            _gA = ffma2(wG[2*_kk],   _hv.x, _gA);                               \
            _gB = ffma2(wG[2*_kk+1], _hv.y, _gB);                               \
            _oA = ffma2(wO[2*_kk],   _hv.x, _oA);                               \
            _oB = ffma2(wO[2*_kk+1], _hv.y, _oB);                               \
        }                                                                       \
        PF;                                                                     \
        u64 _si = addx2(_iA, _iB), _sf = addx2(_fA, _fB);                       \
        u64 _sg = addx2(_gA, _gB), _so = addx2(_oA, _oB);                       \
        float _l, _h2;                                                          \
        upk(_si, _l, _h2); float _di = _l + _h2;                                \
        upk(_sf, _l, _h2); float _df = _l + _h2;                                \
        upk(_sg, _l, _h2); float _dg = _l + _h2;                                \
        upk(_so, _l, _h2); float _do = _l + _h2;                                \
        _di += __shfl_xor_sync(0xFFFFFFFFu, _di, 1);                            \
        _df += __shfl_xor_sync(0xFFFFFFFFu, _df, 1);                            \
        _dg += __shfl_xor_sync(0xFFFFFFFFu, _dg, 1);                            \
        _do += __shfl_xor_sync(0xFFFFFFFFu, _do, 1);                            \
        float _I = sig_ap(_di);                                                 \
        float _F = sig_ap(_df);                                                 \
        float _G = tanh_ap(_dg);                                                \
        float _O = sig_ap(_do);                                                 \
        c = fmaf(_F, c, _I*_G);                                                 \
        float _hn = _O * tanh_ap(c);                                            \
        if (valid) {                                                            \
            if (kh == 0) (HW)[u] = _hn;                                         \
            else         *outp = _hn;                                           \
        }                                                                       \
        outp += D2;                                                             \
        __syncthreads();                                                        \
    } while (0)

    for (int t = 0; t < T - 2; t += 2) {
        { float4 gv = ga; S1_STEP(h_sh[0], h_sh[1], gv,
              { if (gl) ga = *pre; pre += H1; }); }
        { float4 gv = gb; S1_STEP(h_sh[1], h_sh[0], gv,
              { if (gl) gb = *pre; pre += H1; }); }
    }
    { float4 gv = ga; S1_STEP(h_sh[0], h_sh[1], gv, {}); }
    { float4 gv = gb; S1_STEP(h_sh[1], h_sh[0], gv, {}); }
    #undef S1_STEP
}

// ============================================================
// Kernel 3: layer-2 input projections (transposed W in shared).
// Writes [t][u][4] layout (PyTorch gate order within nibble).
// ============================================================
#define GX2_BLOCKS 64
__global__ void __launch_bounds__(256) k_gx2(
    const float* __restrict__ WihF, const float* __restrict__ bF,
    const float* __restrict__ WihB, const float* __restrict__ bB) {
    __shared__ float W[D2 * G2];   // [k][j]
    __shared__ float row[D2];
    const bool bw = (blockIdx.y == 1);
    const float* Wih = bw ? WihB : WihF;
    const float* b   = bw ? bB   : bF;
    float* dst = bw ? g_gx_bw2 : g_gx_fw2;

    for (int i = threadIdx.x; i < G2*D2; i += blockDim.x) {
        int r = i / D2, k = i % D2;
        W[k*G2 + r] = Wih[i];
    }
    int jme = threadIdx.x;
    int gi = (jme < G2) ? (jme / H2) : 0;
    int uj = (jme < G2) ? (jme % H2) : 0;
    float bias = (jme < G2) ? b[jme] : 0.f;
    int dpos = uj*4 + gi;            // [u][gate], PyTorch order i,f,g,o
    __syncthreads();

    const int tpb = T / GX2_BLOCKS;
    const int t0 = blockIdx.x * tpb;
    for (int t = t0; t < t0 + tpb; t++) {
        int src = bw ? (T-1-t) : t;
        __syncthreads();
        for (int i = threadIdx.x; i < D2; i += blockDim.x) row[i] = g_l1[(size_t)src*D2 + i];
        __syncthreads();
        if (jme < G2) {
            float acc = bias;
            #pragma unroll
            for (int k = 0; k < D2; k++) acc += W[k*G2 + jme] * row[k];
            dst[(size_t)t*G2 + dpos] = acc;
        }
    }
}

// ============================================================
// Kernel 4: layer-2 scan — all-4-gates-per-thread, K-half split
// (unchanged from the R11 champion).
// ============================================================
__global__ void __launch_bounds__(128, 1) k_scan2(
    const float* __restrict__ WhhF, const float* __restrict__ h0F, const float* __restrict__ c0F,
    const float* __restrict__ WhhB, const float* __restrict__ h0B, const float* __restrict__ c0B) {
    const bool bw = (blockIdx.x == 1);
    const float* Whh = bw ? WhhB : WhhF;
    const float* h0  = bw ? h0B  : h0F;
    const float* c0  = bw ? c0B  : c0F;
    const float* gx  = bw ? g_gx_bw2 : g_gx_fw2;
    const int off = bw ? H2 : 0;

    __shared__ __align__(16) float h_sh[2][56];   // 14 ulonglong2 rows; [50..56)=0

    const int tid = threadIdx.x;
    const int u  = tid >> 1;
    const int kh = tid & 1;
    const bool valid = (u < H2);
    const int uu = valid ? u : 0;
    const int khb = kh * 7;                        // ulonglong2 base within h row

    u64 wI[14], wF[14], wG[14], wO[14];
    #pragma unroll
    for (int kk = 0; kk < 7; kk++) {
        int base = (khb + kk) * 4;
        #pragma unroll
        for (int g = 0; g < 4; g++) {
            const float* rw = Whh + (g*H2 + uu)*H2;
            float e0 = (valid && base+0 < H2) ? rw[base+0] : 0.f;
            float e1 = (valid && base+1 < H2) ? rw[base+1] : 0.f;
            float e2 = (valid && base+2 < H2) ? rw[base+2] : 0.f;
            float e3 = (valid && base+3 < H2) ? rw[base+3] : 0.f;
            u64 lo = pk(e0, e1), hi = pk(e2, e3);
            if (g == 0) { wI[2*kk] = lo; wI[2*kk+1] = hi; }
            else if (g == 1) { wF[2*kk] = lo; wF[2*kk+1] = hi; }
            else if (g == 2) { wG[2*kk] = lo; wG[2*kk+1] = hi; }
            else { wO[2*kk] = lo; wO[2*kk+1] = hi; }
        }
    }
    const u64 Z = pk(0.f, 0.f);

    if (tid < 56) {
        h_sh[0][tid] = (tid < H2) ? h0[tid] : 0.f;
        h_sh[1][tid] = 0.f;
    }
    float c = valid ? c0[uu] : 0.f;

    const bool gl = valid && (kh == 0);
    const float4* gx4 = (const float4*)gx;
    float4 ga = gl ? gx4[uu]      : make_float4(0.f,0.f,0.f,0.f);
    float4 gb = gl ? gx4[H2 + uu] : make_float4(0.f,0.f,0.f,0.f);
    const float4* pre = gx4 + 2*H2 + uu;
    float* outp = g_l2 + off + uu;
    __syncthreads();

    #define S2_STEP(HR, HW, GV, PF) do {                                        \
        const ulonglong2* _h8 = ((const ulonglong2*)(HR)) + khb;                \
        u64 _iA = pk((GV).x, 0.f), _iB = Z;                                     \
        u64 _fA = pk((GV).y, 0.f), _fB = Z;                                     \
        u64 _gA = pk((GV).z, 0.f), _gB = Z;                                     \
        u64 _oA = pk((GV).w, 0.f), _oB = Z;                                     \
        _Pragma("unroll")                                                       \
        for (int _kk = 0; _kk < 7; _kk++) {                                     \
            ulonglong2 _hv = _h8[_kk];                                          \
            _iA = ffma2(wI[2*_kk],   _hv.x, _iA);                               \
            _iB = ffma2(wI[2*_kk+1], _hv.y, _iB);                               \
            _fA = ffma2(wF[2*_kk],   _hv.x, _fA);                               \
            _fB = ffma2(wF[2*_kk+1], _hv.y, _fB);                               \
            _gA = ffma2(wG[2*_kk],   _hv.x, _gA);                               \
            _gB = ffma2(wG[2*_kk+1], _hv.y, _gB);                               \
            _oA = ffma2(wO[2*_kk],   _hv.x, _oA);                               \
            _oB = ffma2(wO[2*_kk+1], _hv.y, _oB);                               \
        }                                                                       \
        PF;                                                                     \
        u64 _si = addx2(_iA, _iB), _sf = addx2(_fA, _fB);                       \
        u64 _sg = addx2(_gA, _gB), _so = addx2(_oA, _oB);                       \
        float _l, _h2;                                                          \
        upk(_si, _l, _h2); float _di = _l + _h2;                                \
        upk(_sf, _l, _h2); float _df = _l + _h2;                                \
        upk(_sg, _l, _h2); float _dg = _l + _h2;                                \
        upk(_so, _l, _h2); float _do = _l + _h2;                                \
        _di += __shfl_xor_sync(0xFFFFFFFFu, _di, 1);                            \
        _df += __shfl_xor_sync(0xFFFFFFFFu, _df, 1);                            \
        _dg += __shfl_xor_sync(0xFFFFFFFFu, _dg, 1);                            \
        _do += __shfl_xor_sync(0xFFFFFFFFu, _do, 1);                            \
        float _I = sig_ap(_di);                                                 \
        float _F = sig_ap(_df);                                                 \
        float _G = tanh_ap(_dg);                                                \
        float _O = sig_ap(_do);                                                 \
        c = fmaf(_F, c, _I*_G);                                                 \
        float _hn = _O * tanh_ap(c);                                            \
        if (valid) {                                                            \
            if (kh == 0) (HW)[u] = _hn;                                         \
            else         *outp = _hn;                                           \
        }                                                                       \
        outp += D3;                                                             \
        __syncthreads();                                                        \
    } while (0)

    for (int t = 0; t < T - 2; t += 2) {
        { float4 gv = ga; S2_STEP(h_sh[0], h_sh[1], gv,
              { if (gl) ga = *pre; pre += H2; }); }
        { float4 gv = gb; S2_STEP(h_sh[1], h_sh[0], gv,
              { if (gl) gb = *pre; pre += H2; }); }
    }
    { float4 gv = ga; S2_STEP(h_sh[0], h_sh[1], gv, {}); }
    { float4 gv = gb; S2_STEP(h_sh[1], h_sh[0], gv, {}); }
    #undef S2_STEP
}

// ============================================================
// Kernel 5: final MLP (weights in dynamic shared).
// ============================================================
#define MLP_SMEM ((HL*D3 + NT*HL + D3 + HL) * 4)
__global__ void __launch_bounds__(320, 1) k_mlp(
    const float* __restrict__ W1, const float* __restrict__ b1,
    const float* __restrict__ W2, const float* __restrict__ b2,
    float* __restrict__ out) {
    extern __shared__ float sm[];
    float* W1s  = sm;
    float* W2s  = W1s + HL*D3;
    float* rowS = W2s + NT*HL;
    float* hidS = rowS + D3;

    int tid = threadIdx.x;
    for (int i = tid; i < HL*D3; i += blockDim.x) W1s[i] = W1[i];
    for (int i = tid; i < NT*HL; i += blockDim.x) W2s[i] = W2[i];
    __syncthreads();

    for (int t = blockIdx.x; t < T; t += gridDim.x) {
        if (tid < D3) rowS[tid] = g_l2[(size_t)t*D3 + tid];
        __syncthreads();
        if (tid < HL) {
            float acc = b1[tid];
            const float4* wr = (const float4*)(W1s + tid*D3);
            const float4* r4 = (const float4*)rowS;
            #pragma unroll
            for (int k = 0; k < D3/4; k++) {
                float4 wv = wr[k]; float4 rv = r4[k];
                acc += wv.x*rv.x + wv.y*rv.y + wv.z*rv.z + wv.w*rv.w;
            }
            hidS[tid] = tanhf(acc);
        }
        __syncthreads();
        if (tid < NT) {
            float acc = b2[tid];
            const float4* wr = (const float4*)(W2s + tid*HL);
            const float4* h4 = (const float4*)hidS;
            #pragma unroll
            for (int k = 0; k < HL/4; k++) {
                float4 wv = wr[k]; float4 hv = h4[k];
                acc += wv.x*hv.x + wv.y*hv.y + wv.z*hv.z + wv.w*hv.w;
            }
            out[(size_t)t*NT + tid] = acc;
        }
        __syncthreads();
    }
}

// ============================================================
// launch
// ============================================================
extern "C" void kernel_launch(void* const* d_in, const int* in_sizes, int n_in,
                              void* d_out, int out_size) {
    const int*   x   = (const int*)  d_in[0];
    const float* emb = (const float*)d_in[1];

    const float* fw1_Wih = (const float*)d_in[2];
    const float* fw1_Whh = (const float*)d_in[3];
    const float* fw1_b   = (const float*)d_in[4];
    const float* fw1_h0  = (const float*)d_in[5];
    const float* fw1_c0  = (const float*)d_in[6];

    const float* bw1_Wih = (const float*)d_in[7];
    const float* bw1_Whh = (const float*)d_in[8];
    const float* bw1_b   = (const float*)d_in[9];
    const float* bw1_h0  = (const float*)d_in[10];
    const float* bw1_c0  = (const float*)d_in[11];

    const float* fw2_Wih = (const float*)d_in[12];
    const float* fw2_Whh = (const float*)d_in[13];
    const float* fw2_b   = (const float*)d_in[14];
    const float* fw2_h0  = (const float*)d_in[15];
    const float* fw2_c0  = (const float*)d_in[16];

    const float* bw2_Wih = (const float*)d_in[17];
    const float* bw2_Whh = (const float*)d_in[18];
    const float* bw2_b   = (const float*)d_in[19];
    const float* bw2_h0  = (const float*)d_in[20];
    const float* bw2_c0  = (const float*)d_in[21];

    const float* lin1_W = (const float*)d_in[22];
    const float* lin1_b = (const float*)d_in[23];
    const float* lin2_W = (const float*)d_in[24];
    const float* lin2_b = (const float*)d_in[25];

    cudaFuncSetAttribute(k_mlp, cudaFuncAttributeMaxDynamicSharedMemorySize, MLP_SMEM);

    k_gx1<<<T, 128>>>(x, emb, fw1_Wih, fw1_b, bw1_Wih, bw1_b);
    k_scan1<<<2, 64>>>(fw1_Whh, fw1_h0, fw1_c0, bw1_Whh, bw1_h0, bw1_c0);
    k_gx2<<<dim3(GX2_BLOCKS, 2), 256>>>(fw2_Wih, fw2_b, bw2_Wih, bw2_b);
    k_scan2<<<2, 128>>>(fw2_Whh, fw2_h0, fw2_c0, bw2_Whh, bw2_h0, bw2_c0);
    k_mlp<<<148, 320, MLP_SMEM>>>(lin1_W, lin1_b, lin2_W, lin2_b, (float*)d_out);
}

// round 14
// speedup vs baseline: 1.0455x; 1.0455x over previous
#include <cuda_runtime.h>
#include <cuda_bf16.h>
#include <math.h>

#define T  8192
#define E  20
#define H1 30
#define H2 50
#define HL 300
#define NT 50
#define G1 (4*H1)   // 120
#define G2 (4*H2)   // 200
#define D2 (2*H1)   // 60
#define D3 (2*H2)   // 100

// ---- scratch (no allocations allowed) ----
__device__ float g_gx_fw1[T*G1];
__device__ float g_gx_bw1[T*G1];
__device__ float g_l1[T*D2];
// gx2 layout: [t][u][4] with gates in PyTorch order (i,f,g,o) -> one LDG.128/thread
__device__ float g_gx_fw2[T*G2];
__device__ float g_gx_bw2[T*G2];
__device__ float g_l2[T*D3];

typedef unsigned long long u64;

__device__ __forceinline__ u64 pk(float lo, float hi) {
    u64 r; asm("mov.b64 %0, {%1, %2};" : "=l"(r) : "f"(lo), "f"(hi)); return r;
}
__device__ __forceinline__ void upk(u64 v, float& lo, float& hi) {
    asm("mov.b64 {%0, %1}, %2;" : "=f"(lo), "=f"(hi) : "l"(v));
}
__device__ __forceinline__ u64 ffma2(u64 a, u64 b, u64 c) {
    u64 d; asm("fma.rn.f32x2 %0, %1, %2, %3;" : "=l"(d) : "l"(a), "l"(b), "l"(c)); return d;
}
__device__ __forceinline__ u64 addx2(u64 a, u64 b) {
    u64 d; asm("add.rn.f32x2 %0, %1, %2;" : "=l"(d) : "l"(a), "l"(b)); return d;
}
__device__ __forceinline__ float tanh_ap(float x) {
    float y; asm("tanh.approx.f32 %0, %1;" : "=f"(y) : "f"(x)); return y;
}
__device__ __forceinline__ float sig_ap(float x) {
    return fmaf(0.5f, tanh_ap(0.5f*x), 0.5f);
}

// One LSTM step for the (unit, gate-pair) layout — champion scan1 version.
#define LSTM_STEP(HR, HW, GC0, GC1, NHALF, WP0, WP1, OUTP, OUTSTRIDE) do {            \
    const ulonglong2* _h8 = (const ulonglong2*)(HR);                                   \
    u64 _a0 = pk((GC0), 0.f), _a1 = Z, _a2 = Z, _a3 = Z;                               \
    u64 _b0 = pk((GC1), 0.f), _b1 = Z, _b2 = Z, _b3 = Z;                               \
    _Pragma("unroll")                                                                  \
    for (int _kk = 0; _kk < (NHALF); _kk++) {                                          \
        ulonglong2 _hv = _h8[_kk];                                                     \
        if ((_kk & 1) == 0) {                                                          \
            _a0 = ffma2((WP0)[2*_kk],   _hv.x, _a0);                                   \
            _a1 = ffma2((WP0)[2*_kk+1], _hv.y, _a1);                                   \
            _b0 = ffma2((WP1)[2*_kk],   _hv.x, _b0);                                   \
            _b1 = ffma2((WP1)[2*_kk+1], _hv.y, _b1);                                   \
        } else {                                                                       \
            _a2 = ffma2((WP0)[2*_kk],   _hv.x, _a2);                                   \
            _a3 = ffma2((WP0)[2*_kk+1], _hv.y, _a3);                                   \
            _b2 = ffma2((WP1)[2*_kk],   _hv.x, _b2);                                   \
            _b3 = ffma2((WP1)[2*_kk+1], _hv.y, _b3);                                   \
        }                                                                              \
    }                                                                                  \
    u64 _sa = addx2(addx2(_a0, _a1), addx2(_a2, _a3));                                 \
    u64 _sb = addx2(addx2(_b0, _b1), addx2(_b2, _b3));                                 \
    float _d0l,_d0h,_d1l,_d1h; upk(_sa,_d0l,_d0h); upk(_sb,_d1l,_d1h);                 \
    float _d0 = _d0l + _d0h, _d1 = _d1l + _d1h;                                        \
    float _A0 = fmaf(m0,   tanh_ap(s0*_d0),   b0c);                                    \
    float _A1 = fmaf(0.5f, tanh_ap(0.5f*_d1), 0.5f);                                   \
    float _B0 = __shfl_xor_sync(0xFFFFFFFFu, _A0, 1);                                  \
    float _B1 = __shfl_xor_sync(0xFFFFFFFFu, _A1, 1);                                  \
    float _I = p ? _B0 : _A0;                                                          \
    float _F = p ? _B1 : _A1;                                                          \
    float _G = p ? _A0 : _B0;                                                          \
    float _O = p ? _A1 : _B1;                                                          \
    c = fmaf(_F, c, _I*_G);                                                            \
    float _hn = _O * tanh_ap(c);                                                       \
    if (valid) {                                                                       \
        if (p == 0) (HW)[u] = _hn;                                                     \
        else        *(OUTP) = _hn;                                                     \
    }                                                                                  \
    (OUTP) += (OUTSTRIDE);                                                             \
    __syncthreads();                                                                   \
} while (0)

// ============================================================
// Kernel 1: embedding gather + layer-1 input projections.
// ============================================================
__global__ void k_gx1(const int* __restrict__ x, const float* __restrict__ emb,
                      const float* __restrict__ WihF, const float* __restrict__ bF,
                      const float* __restrict__ WihB, const float* __restrict__ bB) {
    __shared__ float e[E];
    int t = blockIdx.x;
    int j = threadIdx.x;
    if (j < E) e[j] = emb[(size_t)x[t] * E + j];
    __syncthreads();
    if (j < G1) {
        float aF = bF[j], aB = bB[j];
        #pragma unroll
        for (int k = 0; k < E; k++) {
            float ev = e[k];
            aF += WihF[j*E + k] * ev;
            aB += WihB[j*E + k] * ev;
        }
        g_gx_fw1[t*G1 + j] = aF;
        g_gx_bw1[(T-1-t)*G1 + j] = aB;
    }
}

// ============================================================
// Kernel 2: layer-1 scan (exact champion config).
// ============================================================
__global__ void __launch_bounds__(64, 1) k_scan1(
    const float* __restrict__ WhhF, const float* __restrict__ h0F, const float* __restrict__ c0F,
    const float* __restrict__ WhhB, const float* __restrict__ h0B, const float* __restrict__ c0B) {
    const bool bw = (blockIdx.x == 1);
    const float* Whh = bw ? WhhB : WhhF;
    const float* h0  = bw ? h0B  : h0F;
    const float* c0  = bw ? c0B  : c0F;
    const float* gx  = bw ? g_gx_bw1 : g_gx_fw1;
    const int off = bw ? H1 : 0;

    __shared__ __align__(16) float h_sh[2][32];

    const int tid = threadIdx.x;
    const int u = tid >> 1;
    const int p = tid & 1;
    const bool valid = (u < H1);
    const int uu = valid ? u : 0;
    const int r0 = p ? (2*H1 + uu) : uu;          // i or g
    const int r1 = p ? (3*H1 + uu) : (H1 + uu);   // f or o

    u64 wp0[16], wp1[16];
    #pragma unroll
    for (int k = 0; k < 15; k++) {
        wp0[k] = pk(valid ? Whh[r0*H1 + 2*k] : 0.f, valid ? Whh[r0*H1 + 2*k + 1] : 0.f);
        wp1[k] = pk(valid ? Whh[r1*H1 + 2*k] : 0.f, valid ? Whh[r1*H1 + 2*k + 1] : 0.f);
    }
    wp0[15] = pk(0.f, 0.f);
    wp1[15] = pk(0.f, 0.f);

    const float s0  = p ? 1.f : 0.5f;
    const float m0  = s0;
    const float b0c = p ? 0.f : 0.5f;
    const u64 Z = pk(0.f, 0.f);

    if (tid < 32) {
        h_sh[0][tid] = (tid < H1) ? h0[tid] : 0.f;
        h_sh[1][tid] = 0.f;
    }
    float c = valid ? c0[uu] : 0.f;

    float ga0 = valid ? gx[r0]      : 0.f;
    float ga1 = valid ? gx[r1]      : 0.f;
    float gb0 = valid ? gx[G1 + r0] : 0.f;
    float gb1 = valid ? gx[G1 + r1] : 0.f;
    const float* pre = gx + 2*G1;
    float* outp = g_l1 + off + uu;
    __syncthreads();

    for (int t = 0; t < T - 2; t += 2) {
        {
            float gc0 = ga0, gc1 = ga1;
            if (valid) { ga0 = pre[r0]; ga1 = pre[r1]; }
            pre += G1;
            LSTM_STEP(h_sh[0], h_sh[1], gc0, gc1, 8, wp0, wp1, outp, D2);
        }
        {
            float gc0 = gb0, gc1 = gb1;
            if (valid) { gb0 = pre[r0]; gb1 = pre[r1]; }
            pre += G1;
            LSTM_STEP(h_sh[1], h_sh[0], gc0, gc1, 8, wp0, wp1, outp, D2);
        }
    }
    LSTM_STEP(h_sh[0], h_sh[1], ga0, ga1, 8, wp0, wp1, outp, D2);
    LSTM_STEP(h_sh[1], h_sh[0], gb0, gb1, 8, wp0, wp1, outp, D2);
}

// ============================================================
// Kernel 3: layer-2 input projections (transposed W in shared).
// Writes [t][u][4] layout (PyTorch gate order within nibble).
// GX2_BLOCKS = 128 (tpb 64) to halve the per-block serial wall.
// ============================================================
#define GX2_BLOCKS 128
__global__ void __launch_bounds__(256) k_gx2(
    const float* __restrict__ WihF, const float* __restrict__ bF,
    const float* __restrict__ WihB, const float* __restrict__ bB) {
    __shared__ float W[D2 * G2];   // [k][j]
    __shared__ float row[D2];
    const bool bw = (blockIdx.y == 1);
    const float* Wih = bw ? WihB : WihF;
    const float* b   = bw ? bB   : bF;
    float* dst = bw ? g_gx_bw2 : g_gx_fw2;

    for (int i = threadIdx.x; i < G2*D2; i += blockDim.x) {
        int r = i / D2, k = i % D2;
        W[k*G2 + r] = Wih[i];
    }
    int jme = threadIdx.x;
    int gi = (jme < G2) ? (jme / H2) : 0;
    int uj = (jme < G2) ? (jme % H2) : 0;
    float bias = (jme < G2) ? b[jme] : 0.f;
    int dpos = uj*4 + gi;            // [u][gate], PyTorch order i,f,g,o
    __syncthreads();

    const int tpb = T / GX2_BLOCKS;
    const int t0 = blockIdx.x * tpb;
    for (int t = t0; t < t0 + tpb; t++) {
        int src = bw ? (T-1-t) : t;
        __syncthreads();
        for (int i = threadIdx.x; i < D2; i += blockDim.x) row[i] = g_l1[(size_t)src*D2 + i];
        __syncthreads();
        if (jme < G2) {
            float acc = bias;
            #pragma unroll
            for (int k = 0; k < D2; k++) acc += W[k*G2 + jme] * row[k];
            dst[(size_t)t*G2 + dpos] = acc;
        }
    }
}

// ============================================================
// Kernel 4: layer-2 scan — all-4-gates-per-thread, K-half split
// (exact R11 champion).
// ============================================================
__global__ void __launch_bounds__(128, 1) k_scan2(
    const float* __restrict__ WhhF, const float* __restrict__ h0F, const float* __restrict__ c0F,
    const float* __restrict__ WhhB, const float* __restrict__ h0B, const float* __restrict__ c0B) {
    const bool bw = (blockIdx.x == 1);
    const float* Whh = bw ? WhhB : WhhF;
    const float* h0  = bw ? h0B  : h0F;
    const float* c0  = bw ? c0B  : c0F;
    const float* gx  = bw ? g_gx_bw2 : g_gx_fw2;
    const int off = bw ? H2 : 0;

    __shared__ __align__(16) float h_sh[2][56];   // 14 ulonglong2 rows; [50..56)=0

    const int tid = threadIdx.x;
    const int u  = tid >> 1;
    const int kh = tid & 1;
    const bool valid = (u < H2);
    const int uu = valid ? u : 0;
    const int khb = kh * 7;                        // ulonglong2 base within h row

    u64 wI[14], wF[14], wG[14], wO[14];
    #pragma unroll
    for (int kk = 0; kk < 7; kk++) {
        int base = (khb + kk) * 4;
        #pragma unroll
        for (int g = 0; g < 4; g++) {
            const float* rw = Whh + (g*H2 + uu)*H2;
            float e0 = (valid && base+0 < H2) ? rw[base+0] : 0.f;
            float e1 = (valid && base+1 < H2) ? rw[base+1] : 0.f;
            float e2 = (valid && base+2 < H2) ? rw[base+2] : 0.f;
            float e3 = (valid && base+3 < H2) ? rw[base+3] : 0.f;
            u64 lo = pk(e0, e1), hi = pk(e2, e3);
            if (g == 0) { wI[2*kk] = lo; wI[2*kk+1] = hi; }
            else if (g == 1) { wF[2*kk] = lo; wF[2*kk+1] = hi; }
            else if (g == 2) { wG[2*kk] = lo; wG[2*kk+1] = hi; }
            else { wO[2*kk] = lo; wO[2*kk+1] = hi; }
        }
    }
    const u64 Z = pk(0.f, 0.f);

    if (tid < 56) {
        h_sh[0][tid] = (tid < H2) ? h0[tid] : 0.f;
        h_sh[1][tid] = 0.f;
    }
    float c = valid ? c0[uu] : 0.f;

    const bool gl = valid && (kh == 0);
    const float4* gx4 = (const float4*)gx;
    float4 ga = gl ? gx4[uu]      : make_float4(0.f,0.f,0.f,0.f);
    float4 gb = gl ? gx4[H2 + uu] : make_float4(0.f,0.f,0.f,0.f);
    const float4* pre = gx4 + 2*H2 + uu;
    float* outp = g_l2 + off + uu;
    __syncthreads();

    #define S2_STEP(HR, HW, GV, PF) do {                                        \
        const ulonglong2* _h8 = ((const ulonglong2*)(HR)) + khb;                \
        u64 _iA = pk((GV).x, 0.f), _iB = Z;                                     \
        u64 _fA = pk((GV).y, 0.f), _fB = Z;                                     \
        u64 _gA = pk((GV).z, 0.f), _gB = Z;                                     \
        u64 _oA = pk((GV).w, 0.f), _oB = Z;                                     \
        _Pragma("unroll")                                                       \
        for (int _kk = 0; _kk < 7; _kk++) {                                     \
            ulonglong2 _hv = _h8[_kk];                                          \
            _iA = ffma2(wI[2*_kk],   _hv.x, _iA);                               \
            _iB = ffma2(wI[2*_kk+1], _hv.y, _iB);                               \
            _fA = ffma2(wF[2*_kk],   _hv.x, _fA);                               \
            _fB = ffma2(wF[2*_kk+1], _hv.y, _fB);                               \
            _gA = ffma2(wG[2*_kk],   _hv.x, _gA);                               \
            _gB = ffma2(wG[2*_kk+1], _hv.y, _gB);                               \
            _oA = ffma2(wO[2*_kk],   _hv.x, _oA);                               \
            _oB = ffma2(wO[2*_kk+1], _hv.y, _oB);                               \
        }                                                                       \
        PF;                                                                     \
        u64 _si = addx2(_iA, _iB), _sf = addx2(_fA, _fB);                       \
        u64 _sg = addx2(_gA, _gB), _so = addx2(_oA, _oB);                       \
        float _l, _h2;                                                          \
        upk(_si, _l, _h2); float _di = _l + _h2;                                \
        upk(_sf, _l, _h2); float _df = _l + _h2;                                \
        upk(_sg, _l, _h2); float _dg = _l + _h2;                                \
        upk(_so, _l, _h2); float _do = _l + _h2;                                \
        _di += __shfl_xor_sync(0xFFFFFFFFu, _di, 1);                            \
        _df += __shfl_xor_sync(0xFFFFFFFFu, _df, 1);                            \
        _dg += __shfl_xor_sync(0xFFFFFFFFu, _dg, 1);                            \
        _do += __shfl_xor_sync(0xFFFFFFFFu, _do, 1);                            \
        float _I = sig_ap(_di);                                                 \
        float _F = sig_ap(_df);                                                 \
        float _G = tanh_ap(_dg);                                                \
        float _O = sig_ap(_do);                                                 \
        c = fmaf(_F, c, _I*_G);                                                 \
        float _hn = _O * tanh_ap(c);                                            \
        if (valid) {                                                            \
            if (kh == 0) (HW)[u] = _hn;                                         \
            else         *outp = _hn;                                           \
        }                                                                       \
        outp += D3;                                                             \
        __syncthreads();                                                        \
    } while (0)

    for (int t = 0; t < T - 2; t += 2) {
        { float4 gv = ga; S2_STEP(h_sh[0], h_sh[1], gv,
              { if (gl) ga = *pre; pre += H2; }); }
        { float4 gv = gb; S2_STEP(h_sh[1], h_sh[0], gv,
              { if (gl) gb = *pre; pre += H2; }); }
    }
    { float4 gv = ga; S2_STEP(h_sh[0], h_sh[1], gv, {}); }
    { float4 gv = gb; S2_STEP(h_sh[1], h_sh[0], gv, {}); }
    #undef S2_STEP
}

// ============================================================
// Kernel 5: final MLP (weights in dynamic shared).
// ============================================================
#define MLP_SMEM ((HL*D3 + NT*HL + D3 + HL) * 4)
__global__ void __launch_bounds__(320, 1) k_mlp(
    const float* __restrict__ W1, const float* __restrict__ b1,
    const float* __restrict__ W2, const float* __restrict__ b2,
    float* __restrict__ out) {
    extern __shared__ float sm[];
    float* W1s  = sm;
    float* W2s  = W1s + HL*D3;
    float* rowS = W2s + NT*HL;
    float* hidS = rowS + D3;

    int tid = threadIdx.x;
    for (int i = tid; i < HL*D3; i += blockDim.x) W1s[i] = W1[i];
    for (int i = tid; i < NT*HL; i += blockDim.x) W2s[i] = W2[i];
    __syncthreads();

    for (int t = blockIdx.x; t < T; t += gridDim.x) {
        if (tid < D3) rowS[tid] = g_l2[(size_t)t*D3 + tid];
        __syncthreads();
        if (tid < HL) {
            float acc = b1[tid];
            const float4* wr = (const float4*)(W1s + tid*D3);
            const float4* r4 = (const float4*)rowS;
            #pragma unroll
            for (int k = 0; k < D3/4; k++) {
                float4 wv = wr[k]; float4 rv = r4[k];
                acc += wv.x*rv.x + wv.y*rv.y + wv.z*rv.z + wv.w*rv.w;
            }
            hidS[tid] = tanhf(acc);
        }
        __syncthreads();
        if (tid < NT) {
            float acc = b2[tid];
            const float4* wr = (const float4*)(W2s + tid*HL);
            const float4* h4 = (const float4*)hidS;
            #pragma unroll
            for (int k = 0; k < HL/4; k++) {
                float4 wv = wr[k]; float4 hv = h4[k];
                acc += wv.x*hv.x + wv.y*hv.y + wv.z*hv.z + wv.w*hv.w;
            }
            out[(size_t)t*NT + tid] = acc;
        }
        __syncthreads();
    }
}

// ============================================================
// launch
// ============================================================
extern "C" void kernel_launch(void* const* d_in, const int* in_sizes, int n_in,
                              void* d_out, int out_size) {
    const int*   x   = (const int*)  d_in[0];
    const float* emb = (const float*)d_in[1];

    const float* fw1_Wih = (const float*)d_in[2];
    const float* fw1_Whh = (const float*)d_in[3];
    const float* fw1_b   = (const float*)d_in[4];
    const float* fw1_h0  = (const float*)d_in[5];
    const float* fw1_c0  = (const float*)d_in[6];

    const float* bw1_Wih = (const float*)d_in[7];
    const float* bw1_Whh = (const float*)d_in[8];
    const float* bw1_b   = (const float*)d_in[9];
    const float* bw1_h0  = (const float*)d_in[10];
    const float* bw1_c0  = (const float*)d_in[11];

    const float* fw2_Wih = (const float*)d_in[12];
    const float* fw2_Whh = (const float*)d_in[13];
    const float* fw2_b   = (const float*)d_in[14];
    const float* fw2_h0  = (const float*)d_in[15];
    const float* fw2_c0  = (const float*)d_in[16];

    const float* bw2_Wih = (const float*)d_in[17];
    const float* bw2_Whh = (const float*)d_in[18];
    const float* bw2_b   = (const float*)d_in[19];
    const float* bw2_h0  = (const float*)d_in[20];
    const float* bw2_c0  = (const float*)d_in[21];

    const float* lin1_W = (const float*)d_in[22];
    const float* lin1_b = (const float*)d_in[23];
    const float* lin2_W = (const float*)d_in[24];
    const float* lin2_b = (const float*)d_in[25];

    cudaFuncSetAttribute(k_mlp, cudaFuncAttributeMaxDynamicSharedMemorySize, MLP_SMEM);

    k_gx1<<<T, 128>>>(x, emb, fw1_Wih, fw1_b, bw1_Wih, bw1_b);
    k_scan1<<<2, 64>>>(fw1_Whh, fw1_h0, fw1_c0, bw1_Whh, bw1_h0, bw1_c0);
    k_gx2<<<dim3(GX2_BLOCKS, 2), 256>>>(fw2_Wih, fw2_b, bw2_Wih, bw2_b);
    k_scan2<<<2, 128>>>(fw2_Whh, fw2_h0, fw2_c0, bw2_Whh, bw2_h0, bw2_c0);
    k_mlp<<<148, 320, MLP_SMEM>>>(lin1_W, lin1_b, lin2_W, lin2_b, (float*)d_out);
}

// round 15
// speedup vs baseline: 1.0508x; 1.0051x over previous
#include <cuda_runtime.h>
#include <cuda_bf16.h>
#include <math.h>

#define T  8192
#define E  20
#define H1 30
#define H2 50
#define HL 300
#define NT 50
#define G1 (4*H1)   // 120
#define G2 (4*H2)   // 200
#define D2 (2*H1)   // 60
#define D3 (2*H2)   // 100

// ---- scratch (no allocations allowed) ----
// gx1: [t][gate-row j] flat (PyTorch gate-major), sigmoid rows pre-scaled x0.5
// gx2: [t][u][4] (PyTorch order i,f,g,o), sigmoid slots pre-scaled x0.5
__device__ float g_gx_fw1[T*G1];
__device__ float g_gx_bw1[T*G1];
__device__ float g_l1[T*D2];
__device__ float g_gx_fw2[T*G2];
__device__ float g_gx_bw2[T*G2];
__device__ float g_l2[T*D3];

typedef unsigned long long u64;

__device__ __forceinline__ u64 pk(float lo, float hi) {
    u64 r; asm("mov.b64 %0, {%1, %2};" : "=l"(r) : "f"(lo), "f"(hi)); return r;
}
__device__ __forceinline__ void upk(u64 v, float& lo, float& hi) {
    asm("mov.b64 {%0, %1}, %2;" : "=f"(lo), "=f"(hi) : "l"(v));
}
__device__ __forceinline__ u64 ffma2(u64 a, u64 b, u64 c) {
    u64 d; asm("fma.rn.f32x2 %0, %1, %2, %3;" : "=l"(d) : "l"(a), "l"(b), "l"(c)); return d;
}
__device__ __forceinline__ u64 addx2(u64 a, u64 b) {
    u64 d; asm("add.rn.f32x2 %0, %1, %2;" : "=l"(d) : "l"(a), "l"(b)); return d;
}
__device__ __forceinline__ float tanh_ap(float x) {
    float y; asm("tanh.approx.f32 %0, %1;" : "=f"(y) : "f"(x)); return y;
}
// pre-scaled sigmoid: argument already multiplied by 0.5
__device__ __forceinline__ float sig_ps(float x) {
    return fmaf(0.5f, tanh_ap(x), 0.5f);
}

// One LSTM step for the (unit, gate-pair) layout — scan1.
// Inputs (gx + weights) pre-scaled: activation needs no argument scaling.
#define LSTM_STEP(HR, HW, GC0, GC1, NHALF, WP0, WP1, OUTP, OUTSTRIDE) do {            \
    const ulonglong2* _h8 = (const ulonglong2*)(HR);                                   \
    u64 _a0 = pk((GC0), 0.f), _a1 = Z, _a2 = Z, _a3 = Z;                               \
    u64 _b0 = pk((GC1), 0.f), _b1 = Z, _b2 = Z, _b3 = Z;                               \
    _Pragma("unroll")                                                                  \
    for (int _kk = 0; _kk < (NHALF); _kk++) {                                          \
        ulonglong2 _hv = _h8[_kk];                                                     \
        if ((_kk & 1) == 0) {                                                          \
            _a0 = ffma2((WP0)[2*_kk],   _hv.x, _a0);                                   \
            _a1 = ffma2((WP0)[2*_kk+1], _hv.y, _a1);                                   \
            _b0 = ffma2((WP1)[2*_kk],   _hv.x, _b0);                                   \
            _b1 = ffma2((WP1)[2*_kk+1], _hv.y, _b1);                                   \
        } else {                                                                       \
            _a2 = ffma2((WP0)[2*_kk],   _hv.x, _a2);                                   \
            _a3 = ffma2((WP0)[2*_kk+1], _hv.y, _a3);                                   \
            _b2 = ffma2((WP1)[2*_kk],   _hv.x, _b2);                                   \
            _b3 = ffma2((WP1)[2*_kk+1], _hv.y, _b3);                                   \
        }                                                                              \
    }                                                                                  \
    u64 _sa = addx2(addx2(_a0, _a1), addx2(_a2, _a3));                                 \
    u64 _sb = addx2(addx2(_b0, _b1), addx2(_b2, _b3));                                 \
    float _d0l,_d0h,_d1l,_d1h; upk(_sa,_d0l,_d0h); upk(_sb,_d1l,_d1h);                 \
    float _d0 = _d0l + _d0h, _d1 = _d1l + _d1h;                                        \
    float _A0 = fmaf(m0, tanh_ap(_d0), b0c);      /* i (sig) or g (tanh) */            \
    float _A1 = sig_ps(_d1);                       /* f or o (sig) */                   \
    float _B0 = __shfl_xor_sync(0xFFFFFFFFu, _A0, 1);                                  \
    float _B1 = __shfl_xor_sync(0xFFFFFFFFu, _A1, 1);                                  \
    float _I = p ? _B0 : _A0;                                                          \
    float _F = p ? _B1 : _A1;                                                          \
    float _G = p ? _A0 : _B0;                                                          \
    float _O = p ? _A1 : _B1;                                                          \
    c = fmaf(_F, c, _I*_G);                                                            \
    float _hn = _O * tanh_ap(c);                                                       \
    if (valid) {                                                                       \
        if (p == 0) (HW)[u] = _hn;                                                     \
        else        *(OUTP) = _hn;                                                     \
    }                                                                                  \
    (OUTP) += (OUTSTRIDE);                                                             \
    __syncthreads();                                                                   \
} while (0)

// ============================================================
// Kernel 1: embedding gather + layer-1 input projections.
// Sigmoid rows (i,f,o) pre-scaled by 0.5.
// ============================================================
__global__ void k_gx1(const int* __restrict__ x, const float* __restrict__ emb,
                      const float* __restrict__ WihF, const float* __restrict__ bF,
                      const float* __restrict__ WihB, const float* __restrict__ bB) {
    __shared__ float e[E];
    int t = blockIdx.x;
    int j = threadIdx.x;
    if (j < E) e[j] = emb[(size_t)x[t] * E + j];
    __syncthreads();
    if (j < G1) {
        int gi = j / H1;
        float scl = (gi == 2) ? 1.f : 0.5f;
        float aF = bF[j], aB = bB[j];
        #pragma unroll
        for (int k = 0; k < E; k++) {
            float ev = e[k];
            aF += WihF[j*E + k] * ev;
            aB += WihB[j*E + k] * ev;
        }
        g_gx_fw1[t*G1 + j] = aF * scl;
        g_gx_bw1[(T-1-t)*G1 + j] = aB * scl;
    }
}

// ============================================================
// Kernel 2: layer-1 scan (champion gate-pair config, pre-scaled).
// ============================================================
__global__ void __launch_bounds__(64, 1) k_scan1(
    const float* __restrict__ WhhF, const float* __restrict__ h0F, const float* __restrict__ c0F,
    const float* __restrict__ WhhB, const float* __restrict__ h0B, const float* __restrict__ c0B) {
    const bool bw = (blockIdx.x == 1);
    const float* Whh = bw ? WhhB : WhhF;
    const float* h0  = bw ? h0B  : h0F;
    const float* c0  = bw ? c0B  : c0F;
    const float* gx  = bw ? g_gx_bw1 : g_gx_fw1;
    const int off = bw ? H1 : 0;

    __shared__ __align__(16) float h_sh[2][32];

    const int tid = threadIdx.x;
    const int u = tid >> 1;
    const int p = tid & 1;
    const bool valid = (u < H1);
    const int uu = valid ? u : 0;
    const int r0 = p ? (2*H1 + uu) : uu;          // i or g
    const int r1 = p ? (3*H1 + uu) : (H1 + uu);   // f or o
    const float scl0 = p ? 1.f : 0.5f;            // g unscaled, i scaled
    const float scl1 = 0.5f;                      // f,o scaled

    u64 wp0[16], wp1[16];
    #pragma unroll
    for (int k = 0; k < 15; k++) {
        wp0[k] = pk(valid ? scl0*Whh[r0*H1 + 2*k] : 0.f, valid ? scl0*Whh[r0*H1 + 2*k + 1] : 0.f);
        wp1[k] = pk(valid ? scl1*Whh[r1*H1 + 2*k] : 0.f, valid ? scl1*Whh[r1*H1 + 2*k + 1] : 0.f);
    }
    wp0[15] = pk(0.f, 0.f);
    wp1[15] = pk(0.f, 0.f);

    const float m0  = p ? 1.f : 0.5f;
    const float b0c = p ? 0.f : 0.5f;
    const u64 Z = pk(0.f, 0.f);

    if (tid < 32) {
        h_sh[0][tid] = (tid < H1) ? h0[tid] : 0.f;
        h_sh[1][tid] = 0.f;
    }
    float c = valid ? c0[uu] : 0.f;

    float ga0 = valid ? gx[r0]      : 0.f;
    float ga1 = valid ? gx[r1]      : 0.f;
    float gb0 = valid ? gx[G1 + r0] : 0.f;
    float gb1 = valid ? gx[G1 + r1] : 0.f;
    const float* pre = gx + 2*G1;
    float* outp = g_l1 + off + uu;
    __syncthreads();

    for (int t = 0; t < T - 2; t += 2) {
        {
            float gc0 = ga0, gc1 = ga1;
            if (valid) { ga0 = pre[r0]; ga1 = pre[r1]; }
            pre += G1;
            LSTM_STEP(h_sh[0], h_sh[1], gc0, gc1, 8, wp0, wp1, outp, D2);
        }
        {
            float gc0 = gb0, gc1 = gb1;
            if (valid) { gb0 = pre[r0]; gb1 = pre[r1]; }
            pre += G1;
            LSTM_STEP(h_sh[1], h_sh[0], gc0, gc1, 8, wp0, wp1, outp, D2);
        }
    }
    LSTM_STEP(h_sh[0], h_sh[1], ga0, ga1, 8, wp0, wp1, outp, D2);
    LSTM_STEP(h_sh[1], h_sh[0], gb0, gb1, 8, wp0, wp1, outp, D2);
}

// ============================================================
// Kernel 3: layer-2 input projections (transposed W in shared).
// Writes [t][u][4] layout; sigmoid slots pre-scaled by 0.5.
// ============================================================
#define GX2_BLOCKS 64
__global__ void __launch_bounds__(256) k_gx2(
    const float* __restrict__ WihF, const float* __restrict__ bF,
    const float* __restrict__ WihB, const float* __restrict__ bB) {
    __shared__ float W[D2 * G2];   // [k][j]
    __shared__ float row[D2];
    const bool bw = (blockIdx.y == 1);
    const float* Wih = bw ? WihB : WihF;
    const float* b   = bw ? bB   : bF;
    float* dst = bw ? g_gx_bw2 : g_gx_fw2;

    for (int i = threadIdx.x; i < G2*D2; i += blockDim.x) {
        int r = i / D2, k = i % D2;
        W[k*G2 + r] = Wih[i];
    }
    int jme = threadIdx.x;
    int gi = (jme < G2) ? (jme / H2) : 0;
    int uj = (jme < G2) ? (jme % H2) : 0;
    float bias = (jme < G2) ? b[jme] : 0.f;
    float scl = (gi == 2) ? 1.f : 0.5f;
    int dpos = uj*4 + gi;            // [u][gate], PyTorch order i,f,g,o
    __syncthreads();

    const int tpb = T / GX2_BLOCKS;
    const int t0 = blockIdx.x * tpb;
    for (int t = t0; t < t0 + tpb; t++) {
        int src = bw ? (T-1-t) : t;
        __syncthreads();
        for (int i = threadIdx.x; i < D2; i += blockDim.x) row[i] = g_l1[(size_t)src*D2 + i];
        __syncthreads();
        if (jme < G2) {
            float acc = bias;
            #pragma unroll
            for (int k = 0; k < D2; k++) acc += W[k*G2 + jme] * row[k];
            dst[(size_t)t*G2 + dpos] = acc * scl;
        }
    }
}

// ============================================================
// Kernel 4: layer-2 scan — all-4-gates-per-thread, K-half split
// (R11 champion), weights/gx pre-scaled for sigmoid gates.
// ============================================================
__global__ void __launch_bounds__(128, 1) k_scan2(
    const float* __restrict__ WhhF, const float* __restrict__ h0F, const float* __restrict__ c0F,
    const float* __restrict__ WhhB, const float* __restrict__ h0B, const float* __restrict__ c0B) {
    const bool bw = (blockIdx.x == 1);
    const float* Whh = bw ? WhhB : WhhF;
    const float* h0  = bw ? h0B  : h0F;
    const float* c0  = bw ? c0B  : c0F;
    const float* gx  = bw ? g_gx_bw2 : g_gx_fw2;
    const int off = bw ? H2 : 0;

    __shared__ __align__(16) float h_sh[2][56];   // 14 ulonglong2 rows; [50..56)=0

    const int tid = threadIdx.x;
    const int u  = tid >> 1;
    const int kh = tid & 1;
    const bool valid = (u < H2);
    const int uu = valid ? u : 0;
    const int khb = kh * 7;                        // ulonglong2 base within h row

    u64 wI[14], wF[14], wG[14], wO[14];
    #pragma unroll
    for (int kk = 0; kk < 7; kk++) {
        int base = (khb + kk) * 4;
        #pragma unroll
        for (int g = 0; g < 4; g++) {
            const float* rw = Whh + (g*H2 + uu)*H2;
            float scl = (g == 2) ? 1.f : 0.5f;     // i,f,o pre-scaled
            float e0 = (valid && base+0 < H2) ? scl*rw[base+0] : 0.f;
            float e1 = (valid && base+1 < H2) ? scl*rw[base+1] : 0.f;
            float e2 = (valid && base+2 < H2) ? scl*rw[base+2] : 0.f;
            float e3 = (valid && base+3 < H2) ? scl*rw[base+3] : 0.f;
            u64 lo = pk(e0, e1), hi = pk(e2, e3);
            if (g == 0) { wI[2*kk] = lo; wI[2*kk+1] = hi; }
            else if (g == 1) { wF[2*kk] = lo; wF[2*kk+1] = hi; }
            else if (g == 2) { wG[2*kk] = lo; wG[2*kk+1] = hi; }
            else { wO[2*kk] = lo; wO[2*kk+1] = hi; }
        }
    }
    const u64 Z = pk(0.f, 0.f);

    if (tid < 56) {
        h_sh[0][tid] = (tid < H2) ? h0[tid] : 0.f;
        h_sh[1][tid] = 0.f;
    }
    float c = valid ? c0[uu] : 0.f;

    const bool gl = valid && (kh == 0);
    const float4* gx4 = (const float4*)gx;
    float4 ga = gl ? gx4[uu]      : make_float4(0.f,0.f,0.f,0.f);
    float4 gb = gl ? gx4[H2 + uu] : make_float4(0.f,0.f,0.f,0.f);
    const float4* pre = gx4 + 2*H2 + uu;
    float* outp = g_l2 + off + uu;
    __syncthreads();

    #define S2_STEP(HR, HW, GV, PF) do {                                        \
        const ulonglong2* _h8 = ((const ulonglong2*)(HR)) + khb;                \
        u64 _iA = pk((GV).x, 0.f), _iB = Z;                                     \
        u64 _fA = pk((GV).y, 0.f), _fB = Z;                                     \
        u64 _gA = pk((GV).z, 0.f), _gB = Z;                                     \
        u64 _oA = pk((GV).w, 0.f), _oB = Z;                                     \
        _Pragma("unroll")                                                       \
        for (int _kk = 0; _kk < 7; _kk++) {                                     \
            ulonglong2 _hv = _h8[_kk];                                          \
            _iA = ffma2(wI[2*_kk],   _hv.x, _iA);                               \
            _iB = ffma2(wI[2*_kk+1], _hv.y, _iB);                               \
            _fA = ffma2(wF[2*_kk],   _hv.x, _fA);                               \
            _fB = ffma2(wF[2*_kk+1], _hv.y, _fB);                               \
            _gA = ffma2(wG[2*_kk],   _hv.x, _gA);                               \
            _gB = ffma2(wG[2*_kk+1], _hv.y, _gB);                               \
            _oA = ffma2(wO[2*_kk],   _hv.x, _oA);                               \
            _oB = ffma2(wO[2*_kk+1], _hv.y, _oB);                               \
        }                                                                       \
        PF;                                                                     \
        u64 _si = addx2(_iA, _iB), _sf = addx2(_fA, _fB);                       \
        u64 _sg = addx2(_gA, _gB), _so = addx2(_oA, _oB);                       \
        float _l, _h2;                                                          \
        upk(_si, _l, _h2); float _di = _l + _h2;                                \
        upk(_sf, _l, _h2); float _df = _l + _h2;                                \
        upk(_sg, _l, _h2); float _dg = _l + _h2;                                \
        upk(_so, _l, _h2); float _do = _l + _h2;                                \
        _di += __shfl_xor_sync(0xFFFFFFFFu, _di, 1);                            \
        _df += __shfl_xor_sync(0xFFFFFFFFu, _df, 1);                            \
        _dg += __shfl_xor_sync(0xFFFFFFFFu, _dg, 1);                            \
        _do += __shfl_xor_sync(0xFFFFFFFFu, _do, 1);                            \
        float _I = sig_ps(_di);                                                 \
        float _F = sig_ps(_df);                                                 \
        float _G = tanh_ap(_dg);                                                \
        float _O = sig_ps(_do);                                                 \
        c = fmaf(_F, c, _I*_G);                                                 \
        float _hn = _O * tanh_ap(c);                                            \
        if (valid) {                                                            \
            if (kh == 0) (HW)[u] = _hn;                                         \
            else         *outp = _hn;                                           \
        }                                                                       \
        outp += D3;                                                             \
        __syncthreads();                                                        \
    } while (0)

    for (int t = 0; t < T - 2; t += 2) {
        { float4 gv = ga; S2_STEP(h_sh[0], h_sh[1], gv,
              { if (gl) ga = *pre; pre += H2; }); }
        { float4 gv = gb; S2_STEP(h_sh[1], h_sh[0], gv,
              { if (gl) gb = *pre; pre += H2; }); }
    }
    { float4 gv = ga; S2_STEP(h_sh[0], h_sh[1], gv, {}); }
    { float4 gv = gb; S2_STEP(h_sh[1], h_sh[0], gv, {}); }
    #undef S2_STEP
}

// ============================================================
// Kernel 5: final MLP (weights in dynamic shared).
// ============================================================
#define MLP_SMEM ((HL*D3 + NT*HL + D3 + HL) * 4)
__global__ void __launch_bounds__(320, 1) k_mlp(
    const float* __restrict__ W1, const float* __restrict__ b1,
    const float* __restrict__ W2, const float* __restrict__ b2,
    float* __restrict__ out) {
    extern __shared__ float sm[];
    float* W1s  = sm;
    float* W2s  = W1s + HL*D3;
    float* rowS = W2s + NT*HL;
    float* hidS = rowS + D3;

    int tid = threadIdx.x;
    for (int i = tid; i < HL*D3; i += blockDim.x) W1s[i] = W1[i];
    for (int i = tid; i < NT*HL; i += blockDim.x) W2s[i] = W2[i];
    __syncthreads();

    for (int t = blockIdx.x; t < T; t += gridDim.x) {
        if (tid < D3) rowS[tid] = g_l2[(size_t)t*D3 + tid];
        __syncthreads();
        if (tid < HL) {
            float acc = b1[tid];
            const float4* wr = (const float4*)(W1s + tid*D3);
            const float4* r4 = (const float4*)rowS;
            #pragma unroll
            for (int k = 0; k < D3/4; k++) {
                float4 wv = wr[k]; float4 rv = r4[k];
                acc += wv.x*rv.x + wv.y*rv.y + wv.z*rv.z + wv.w*rv.w;
            }
            hidS[tid] = tanhf(acc);
        }
        __syncthreads();
        if (tid < NT) {
            float acc = b2[tid];
            const float4* wr = (const float4*)(W2s + tid*HL);
            const float4* h4 = (const float4*)hidS;
            #pragma unroll
            for (int k = 0; k < HL/4; k++) {
                float4 wv = wr[k]; float4 hv = h4[k];
                acc += wv.x*hv.x + wv.y*hv.y + wv.z*hv.z + wv.w*hv.w;
            }
            out[(size_t)t*NT + tid] = acc;
        }
        __syncthreads();
    }
}

// ============================================================
// launch
// ============================================================
extern "C" void kernel_launch(void* const* d_in, const int* in_sizes, int n_in,
                              void* d_out, int out_size) {
    const int*   x   = (const int*)  d_in[0];
    const float* emb = (const float*)d_in[1];

    const float* fw1_Wih = (const float*)d_in[2];
    const float* fw1_Whh = (const float*)d_in[3];
    const float* fw1_b   = (const float*)d_in[4];
    const float* fw1_h0  = (const float*)d_in[5];
    const float* fw1_c0  = (const float*)d_in[6];

    const float* bw1_Wih = (const float*)d_in[7];
    const float* bw1_Whh = (const float*)d_in[8];
    const float* bw1_b   = (const float*)d_in[9];
    const float* bw1_h0  = (const float*)d_in[10];
    const float* bw1_c0  = (const float*)d_in[11];

    const float* fw2_Wih = (const float*)d_in[12];
    const float* fw2_Whh = (const float*)d_in[13];
    const float* fw2_b   = (const float*)d_in[14];
    const float* fw2_h0  = (const float*)d_in[15];
    const float* fw2_c0  = (const float*)d_in[16];

    const float* bw2_Wih = (const float*)d_in[17];
    const float* bw2_Whh = (const float*)d_in[18];
    const float* bw2_b   = (const float*)d_in[19];
    const float* bw2_h0  = (const float*)d_in[20];
    const float* bw2_c0  = (const float*)d_in[21];

    const float* lin1_W = (const float*)d_in[22];
    const float* lin1_b = (const float*)d_in[23];
    const float* lin2_W = (const float*)d_in[24];
    const float* lin2_b = (const float*)d_in[25];

    cudaFuncSetAttribute(k_mlp, cudaFuncAttributeMaxDynamicSharedMemorySize, MLP_SMEM);

    k_gx1<<<T, 128>>>(x, emb, fw1_Wih, fw1_b, bw1_Wih, bw1_b);
    k_scan1<<<2, 64>>>(fw1_Whh, fw1_h0, fw1_c0, bw1_Whh, bw1_h0, bw1_c0);
    k_gx2<<<dim3(GX2_BLOCKS, 2), 256>>>(fw2_Wih, fw2_b, bw2_Wih, bw2_b);
    k_scan2<<<2, 128>>>(fw2_Whh, fw2_h0, fw2_c0, bw2_Whh, bw2_h0, bw2_c0);
    k_mlp<<<148, 320, MLP_SMEM>>>(lin1_W, lin1_b, lin2_W, lin2_b, (float*)d_out);
}

// round 16
// speedup vs baseline: 1.0509x; 1.0001x over previous
#include <cuda_runtime.h>
#include <cuda_bf16.h>
#include <math.h>

#define T  8192
#define E  20
#define H1 30
#define H2 50
#define HL 300
#define NT 50
#define G1 (4*H1)   // 120
#define G2 (4*H2)   // 200
#define D2 (2*H1)   // 60
#define D3 (2*H2)   // 100

// ---- scratch (no allocations allowed) ----
__device__ float g_gx_fw1[T*G1];
__device__ float g_gx_bw1[T*G1];
__device__ float g_l1[T*D2];
// gx2 layout: [t][u][4] with gates in PyTorch order (i,f,g,o) -> one LDG.128/thread
__device__ float g_gx_fw2[T*G2];
__device__ float g_gx_bw2[T*G2];
__device__ float g_l2[T*D3];

typedef unsigned long long u64;

__device__ __forceinline__ u64 pk(float lo, float hi) {
    u64 r; asm("mov.b64 %0, {%1, %2};" : "=l"(r) : "f"(lo), "f"(hi)); return r;
}
__device__ __forceinline__ void upk(u64 v, float& lo, float& hi) {
    asm("mov.b64 {%0, %1}, %2;" : "=f"(lo), "=f"(hi) : "l"(v));
}
__device__ __forceinline__ u64 ffma2(u64 a, u64 b, u64 c) {
    u64 d; asm("fma.rn.f32x2 %0, %1, %2, %3;" : "=l"(d) : "l"(a), "l"(b), "l"(c)); return d;
}
__device__ __forceinline__ u64 addx2(u64 a, u64 b) {
    u64 d; asm("add.rn.f32x2 %0, %1, %2;" : "=l"(d) : "l"(a), "l"(b)); return d;
}
__device__ __forceinline__ float tanh_ap(float x) {
    float y; asm("tanh.approx.f32 %0, %1;" : "=f"(y) : "f"(x)); return y;
}
__device__ __forceinline__ float sig_ap(float x) {
    return fmaf(0.5f, tanh_ap(0.5f*x), 0.5f);
}

// One LSTM step for the (unit, gate-pair) layout — champion scan1 version.
#define LSTM_STEP(HR, HW, GC0, GC1, NHALF, WP0, WP1, OUTP, OUTSTRIDE) do {            \
    const ulonglong2* _h8 = (const ulonglong2*)(HR);                                   \
    u64 _a0 = pk((GC0), 0.f), _a1 = Z, _a2 = Z, _a3 = Z;                               \
    u64 _b0 = pk((GC1), 0.f), _b1 = Z, _b2 = Z, _b3 = Z;                               \
    _Pragma("unroll")                                                                  \
    for (int _kk = 0; _kk < (NHALF); _kk++) {                                          \
        ulonglong2 _hv = _h8[_kk];                                                     \
        if ((_kk & 1) == 0) {                                                          \
            _a0 = ffma2((WP0)[2*_kk],   _hv.x, _a0);                                   \
            _a1 = ffma2((WP0)[2*_kk+1], _hv.y, _a1);                                   \
            _b0 = ffma2((WP1)[2*_kk],   _hv.x, _b0);                                   \
            _b1 = ffma2((WP1)[2*_kk+1], _hv.y, _b1);                                   \
        } else {                                                                       \
            _a2 = ffma2((WP0)[2*_kk],   _hv.x, _a2);                                   \
            _a3 = ffma2((WP0)[2*_kk+1], _hv.y, _a3);                                   \
            _b2 = ffma2((WP1)[2*_kk],   _hv.x, _b2);                                   \
            _b3 = ffma2((WP1)[2*_kk+1], _hv.y, _b3);                                   \
        }                                                                              \
    }                                                                                  \
    u64 _sa = addx2(addx2(_a0, _a1), addx2(_a2, _a3));                                 \
    u64 _sb = addx2(addx2(_b0, _b1), addx2(_b2, _b3));                                 \
    float _d0l,_d0h,_d1l,_d1h; upk(_sa,_d0l,_d0h); upk(_sb,_d1l,_d1h);                 \
    float _d0 = _d0l + _d0h, _d1 = _d1l + _d1h;                                        \
    float _A0 = fmaf(m0,   tanh_ap(s0*_d0),   b0c);                                    \
    float _A1 = fmaf(0.5f, tanh_ap(0.5f*_d1), 0.5f);                                   \
    float _B0 = __shfl_xor_sync(0xFFFFFFFFu, _A0, 1);                                  \
    float _B1 = __shfl_xor_sync(0xFFFFFFFFu, _A1, 1);                                  \
    float _I = p ? _B0 : _A0;                                                          \
    float _F = p ? _B1 : _A1;                                                          \
    float _G = p ? _A0 : _B0;                                                          \
    float _O = p ? _A1 : _B1;                                                          \
    c = fmaf(_F, c, _I*_G);                                                            \
    float _hn = _O * tanh_ap(c);                                                       \
    if (valid) {                                                                       \
        if (p == 0) (HW)[u] = _hn;                                                     \
        else        *(OUTP) = _hn;                                                     \
    }                                                                                  \
    (OUTP) += (OUTSTRIDE);                                                             \
    __syncthreads();                                                                   \
} while (0)

// ============================================================
// Kernel 1: embedding gather + layer-1 input projections.
// ============================================================
__global__ void k_gx1(const int* __restrict__ x, const float* __restrict__ emb,
                      const float* __restrict__ WihF, const float* __restrict__ bF,
                      const float* __restrict__ WihB, const float* __restrict__ bB) {
    __shared__ float e[E];
    int t = blockIdx.x;
    int j = threadIdx.x;
    if (j < E) e[j] = emb[(size_t)x[t] * E + j];
    __syncthreads();
    if (j < G1) {
        float aF = bF[j], aB = bB[j];
        #pragma unroll
        for (int k = 0; k < E; k++) {
            float ev = e[k];
            aF += WihF[j*E + k] * ev;
            aB += WihB[j*E + k] * ev;
        }
        g_gx_fw1[t*G1 + j] = aF;
        g_gx_bw1[(T-1-t)*G1 + j] = aB;
    }
}

// ============================================================
// Kernel 2: layer-1 scan (champion gate-pair config).
// ============================================================
__global__ void __launch_bounds__(64, 1) k_scan1(
    const float* __restrict__ WhhF, const float* __restrict__ h0F, const float* __restrict__ c0F,
    const float* __restrict__ WhhB, const float* __restrict__ h0B, const float* __restrict__ c0B) {
    const bool bw = (blockIdx.x == 1);
    const float* Whh = bw ? WhhB : WhhF;
    const float* h0  = bw ? h0B  : h0F;
    const float* c0  = bw ? c0B  : c0F;
    const float* gx  = bw ? g_gx_bw1 : g_gx_fw1;
    const int off = bw ? H1 : 0;

    __shared__ __align__(16) float h_sh[2][32];

    const int tid = threadIdx.x;
    const int u = tid >> 1;
    const int p = tid & 1;
    const bool valid = (u < H1);
    const int uu = valid ? u : 0;
    const int r0 = p ? (2*H1 + uu) : uu;          // i or g
    const int r1 = p ? (3*H1 + uu) : (H1 + uu);   // f or o

    u64 wp0[16], wp1[16];
    #pragma unroll
    for (int k = 0; k < 15; k++) {
        wp0[k] = pk(valid ? Whh[r0*H1 + 2*k] : 0.f, valid ? Whh[r0*H1 + 2*k + 1] : 0.f);
        wp1[k] = pk(valid ? Whh[r1*H1 + 2*k] : 0.f, valid ? Whh[r1*H1 + 2*k + 1] : 0.f);
    }
    wp0[15] = pk(0.f, 0.f);
    wp1[15] = pk(0.f, 0.f);

    const float s0  = p ? 1.f : 0.5f;
    const float m0  = s0;
    const float b0c = p ? 0.f : 0.5f;
    const u64 Z = pk(0.f, 0.f);

    if (tid < 32) {
        h_sh[0][tid] = (tid < H1) ? h0[tid] : 0.f;
        h_sh[1][tid] = 0.f;
    }
    float c = valid ? c0[uu] : 0.f;

    float ga0 = valid ? gx[r0]      : 0.f;
    float ga1 = valid ? gx[r1]      : 0.f;
    float gb0 = valid ? gx[G1 + r0] : 0.f;
    float gb1 = valid ? gx[G1 + r1] : 0.f;
    const float* pre = gx + 2*G1;
    float* outp = g_l1 + off + uu;
    __syncthreads();

    for (int t = 0; t < T - 2; t += 2) {
        {
            float gc0 = ga0, gc1 = ga1;
            if (valid) { ga0 = pre[r0]; ga1 = pre[r1]; }
            pre += G1;
            LSTM_STEP(h_sh[0], h_sh[1], gc0, gc1, 8, wp0, wp1, outp, D2);
        }
        {
            float gc0 = gb0, gc1 = gb1;
            if (valid) { gb0 = pre[r0]; gb1 = pre[r1]; }
            pre += G1;
            LSTM_STEP(h_sh[1], h_sh[0], gc0, gc1, 8, wp0, wp1, outp, D2);
        }
    }
    LSTM_STEP(h_sh[0], h_sh[1], ga0, ga1, 8, wp0, wp1, outp, D2);
    LSTM_STEP(h_sh[1], h_sh[0], gb0, gb1, 8, wp0, wp1, outp, D2);
}

// ============================================================
// Kernel 3: layer-2 input projections (transposed W in shared).
// Writes [t][u][4] layout (PyTorch gate order within nibble).
// ============================================================
#define GX2_BLOCKS 64
__global__ void __launch_bounds__(256) k_gx2(
    const float* __restrict__ WihF, const float* __restrict__ bF,
    const float* __restrict__ WihB, const float* __restrict__ bB) {
    __shared__ float W[D2 * G2];   // [k][j]
    __shared__ float row[D2];
    const bool bw = (blockIdx.y == 1);
    const float* Wih = bw ? WihB : WihF;
    const float* b   = bw ? bB   : bF;
    float* dst = bw ? g_gx_bw2 : g_gx_fw2;

    for (int i = threadIdx.x; i < G2*D2; i += blockDim.x) {
        int r = i / D2, k = i % D2;
        W[k*G2 + r] = Wih[i];
    }
    int jme = threadIdx.x;
    int gi = (jme < G2) ? (jme / H2) : 0;
    int uj = (jme < G2) ? (jme % H2) : 0;
    float bias = (jme < G2) ? b[jme] : 0.f;
    int dpos = uj*4 + gi;            // [u][gate], PyTorch order i,f,g,o
    __syncthreads();

    const int tpb = T / GX2_BLOCKS;
    const int t0 = blockIdx.x * tpb;
    for (int t = t0; t < t0 + tpb; t++) {
        int src = bw ? (T-1-t) : t;
        __syncthreads();
        for (int i = threadIdx.x; i < D2; i += blockDim.x) row[i] = g_l1[(size_t)src*D2 + i];
        __syncthreads();
        if (jme < G2) {
            float acc = bias;
            #pragma unroll
            for (int k = 0; k < D2; k++) acc += W[k*G2 + jme] * row[k];
            dst[(size_t)t*G2 + dpos] = acc;
        }
    }
}

// ============================================================
// Kernel 4: layer-2 scan — all-4-gates-per-thread, K-half split
// (R11 champion).
// ============================================================
__global__ void __launch_bounds__(128, 1) k_scan2(
    const float* __restrict__ WhhF, const float* __restrict__ h0F, const float* __restrict__ c0F,
    const float* __restrict__ WhhB, const float* __restrict__ h0B, const float* __restrict__ c0B) {
    const bool bw = (blockIdx.x == 1);
    const float* Whh = bw ? WhhB : WhhF;
    const float* h0  = bw ? h0B  : h0F;
    const float* c0  = bw ? c0B  : c0F;
    const float* gx  = bw ? g_gx_bw2 : g_gx_fw2;
    const int off = bw ? H2 : 0;

    __shared__ __align__(16) float h_sh[2][56];   // 14 ulonglong2 rows; [50..56)=0

    const int tid = threadIdx.x;
    const int u  = tid >> 1;
    const int kh = tid & 1;
    const bool valid = (u < H2);
    const int uu = valid ? u : 0;
    const int khb = kh * 7;                        // ulonglong2 base within h row

    u64 wI[14], wF[14], wG[14], wO[14];
    #pragma unroll
    for (int kk = 0; kk < 7; kk++) {
        int base = (khb + kk) * 4;
        #pragma unroll
        for (int g = 0; g < 4; g++) {
            const float* rw = Whh + (g*H2 + uu)*H2;
            float e0 = (valid && base+0 < H2) ? rw[base+0] : 0.f;
            float e1 = (valid && base+1 < H2) ? rw[base+1] : 0.f;
            float e2 = (valid && base+2 < H2) ? rw[base+2] : 0.f;
            float e3 = (valid && base+3 < H2) ? rw[base+3] : 0.f;
            u64 lo = pk(e0, e1), hi = pk(e2, e3);
            if (g == 0) { wI[2*kk] = lo; wI[2*kk+1] = hi; }
            else if (g == 1) { wF[2*kk] = lo; wF[2*kk+1] = hi; }
            else if (g == 2) { wG[2*kk] = lo; wG[2*kk+1] = hi; }
            else { wO[2*kk] = lo; wO[2*kk+1] = hi; }
        }
    }
    const u64 Z = pk(0.f, 0.f);

    if (tid < 56) {
        h_sh[0][tid] = (tid < H2) ? h0[tid] : 0.f;
        h_sh[1][tid] = 0.f;
    }
    float c = valid ? c0[uu] : 0.f;

    const bool gl = valid && (kh == 0);
    const float4* gx4 = (const float4*)gx;
    float4 ga = gl ? gx4[uu]      : make_float4(0.f,0.f,0.f,0.f);
    float4 gb = gl ? gx4[H2 + uu] : make_float4(0.f,0.f,0.f,0.f);
    const float4* pre = gx4 + 2*H2 + uu;
    float* outp = g_l2 + off + uu;
    __syncthreads();

    #define S2_STEP(HR, HW, GV, PF) do {                                        \
        const ulonglong2* _h8 = ((const ulonglong2*)(HR)) + khb;                \
        u64 _iA = pk((GV).x, 0.f), _iB = Z;                                     \
        u64 _fA = pk((GV).y, 0.f), _fB = Z;                                     \
        u64 _gA = pk((GV).z, 0.f), _gB = Z;                                     \
        u64 _oA = pk((GV).w, 0.f), _oB = Z;                                     \
        _Pragma("unroll")                                                       \
        for (int _kk = 0; _kk < 7; _kk++) {                                     \
            ulonglong2 _hv = _h8[_kk];                                          \
            _iA = ffma2(wI[2*_kk],   _hv.x, _iA);                               \
            _iB = ffma2(wI[2*_kk+1], _hv.y, _iB);                               \
            _fA = ffma2(wF[2*_kk],   _hv.x, _fA);                               \
            _fB = ffma2(wF[2*_kk+1], _hv.y, _fB);                               \
            _gA = ffma2(wG[2*_kk],   _hv.x, _gA);                               \
            _gB = ffma2(wG[2*_kk+1], _hv.y, _gB);                               \
            _oA = ffma2(wO[2*_kk],   _hv.x, _oA);                               \
            _oB = ffma2(wO[2*_kk+1], _hv.y, _oB);                               \
        }                                                                       \
        PF;                                                                     \
        u64 _si = addx2(_iA, _iB), _sf = addx2(_fA, _fB);                       \
        u64 _sg = addx2(_gA, _gB), _so = addx2(_oA, _oB);                       \
        float _l, _h2;                                                          \
        upk(_si, _l, _h2); float _di = _l + _h2;                                \
        upk(_sf, _l, _h2); float _df = _l + _h2;                                \
        upk(_sg, _l, _h2); float _dg = _l + _h2;                                \
        upk(_so, _l, _h2); float _do = _l + _h2;                                \
        _di += __shfl_xor_sync(0xFFFFFFFFu, _di, 1);                            \
        _df += __shfl_xor_sync(0xFFFFFFFFu, _df, 1);                            \
        _dg += __shfl_xor_sync(0xFFFFFFFFu, _dg, 1);                            \
        _do += __shfl_xor_sync(0xFFFFFFFFu, _do, 1);                            \
        float _I = sig_ap(_di);                                                 \
        float _F = sig_ap(_df);                                                 \
        float _G = tanh_ap(_dg);                                                \
        float _O = sig_ap(_do);                                                 \
        c = fmaf(_F, c, _I*_G);                                                 \
        float _hn = _O * tanh_ap(c);                                            \
        if (valid) {                                                            \
            if (kh == 0) (HW)[u] = _hn;                                         \
            else         *outp = _hn;                                           \
        }                                                                       \
        outp += D3;                                                             \
        __syncthreads();                                                        \
    } while (0)

    for (int t = 0; t < T - 2; t += 2) {
        { float4 gv = ga; S2_STEP(h_sh[0], h_sh[1], gv,
              { if (gl) ga = *pre; pre += H2; }); }
        { float4 gv = gb; S2_STEP(h_sh[1], h_sh[0], gv,
              { if (gl) gb = *pre; pre += H2; }); }
    }
    { float4 gv = ga; S2_STEP(h_sh[0], h_sh[1], gv, {}); }
    { float4 gv = gb; S2_STEP(h_sh[1], h_sh[0], gv, {}); }
    #undef S2_STEP
}

// ============================================================
// Kernel 5: final MLP (weights in dynamic shared).
// ============================================================
#define MLP_SMEM ((HL*D3 + NT*HL + D3 + HL) * 4)
__global__ void __launch_bounds__(320, 1) k_mlp(
    const float* __restrict__ W1, const float* __restrict__ b1,
    const float* __restrict__ W2, const float* __restrict__ b2,
    float* __restrict__ out) {
    extern __shared__ float sm[];
    float* W1s  = sm;
    float* W2s  = W1s + HL*D3;
    float* rowS = W2s + NT*HL;
    float* hidS = rowS + D3;

    int tid = threadIdx.x;
    for (int i = tid; i < HL*D3; i += blockDim.x) W1s[i] = W1[i];
    for (int i = tid; i < NT*HL; i += blockDim.x) W2s[i] = W2[i];
    __syncthreads();

    for (int t = blockIdx.x; t < T; t += gridDim.x) {
        if (tid < D3) rowS[tid] = g_l2[(size_t)t*D3 + tid];
        __syncthreads();
        if (tid < HL) {
            float acc = b1[tid];
            const float4* wr = (const float4*)(W1s + tid*D3);
            const float4* r4 = (const float4*)rowS;
            #pragma unroll
            for (int k = 0; k < D3/4; k++) {
                float4 wv = wr[k]; float4 rv = r4[k];
                acc += wv.x*rv.x + wv.y*rv.y + wv.z*rv.z + wv.w*rv.w;
            }
            hidS[tid] = tanhf(acc);
        }
        __syncthreads();
        if (tid < NT) {
            float acc = b2[tid];
            const float4* wr = (const float4*)(W2s + tid*HL);
            const float4* h4 = (const float4*)hidS;
            #pragma unroll
            for (int k = 0; k < HL/4; k++) {
                float4 wv = wr[k]; float4 hv = h4[k];
                acc += wv.x*hv.x + wv.y*hv.y + wv.z*hv.z + wv.w*hv.w;
            }
            out[(size_t)t*NT + tid] = acc;
        }
        __syncthreads();
    }
}

// ============================================================
// launch
// ============================================================
extern "C" void kernel_launch(void* const* d_in, const int* in_sizes, int n_in,
                              void* d_out, int out_size) {
    const int*   x   = (const int*)  d_in[0];
    const float* emb = (const float*)d_in[1];

    const float* fw1_Wih = (const float*)d_in[2];
    const float* fw1_Whh = (const float*)d_in[3];
    const float* fw1_b   = (const float*)d_in[4];
    const float* fw1_h0  = (const float*)d_in[5];
    const float* fw1_c0  = (const float*)d_in[6];

    const float* bw1_Wih = (const float*)d_in[7];
    const float* bw1_Whh = (const float*)d_in[8];
    const float* bw1_b   = (const float*)d_in[9];
    const float* bw1_h0  = (const float*)d_in[10];
    const float* bw1_c0  = (const float*)d_in[11];

    const float* fw2_Wih = (const float*)d_in[12];
    const float* fw2_Whh = (const float*)d_in[13];
    const float* fw2_b   = (const float*)d_in[14];
    const float* fw2_h0  = (const float*)d_in[15];
    const float* fw2_c0  = (const float*)d_in[16];

    const float* bw2_Wih = (const float*)d_in[17];
    const float* bw2_Whh = (const float*)d_in[18];
    const float* bw2_b   = (const float*)d_in[19];
    const float* bw2_h0  = (const float*)d_in[20];
    const float* bw2_c0  = (const float*)d_in[21];

    const float* lin1_W = (const float*)d_in[22];
    const float* lin1_b = (const float*)d_in[23];
    const float* lin2_W = (const float*)d_in[24];
    const float* lin2_b = (const float*)d_in[25];

    cudaFuncSetAttribute(k_mlp, cudaFuncAttributeMaxDynamicSharedMemorySize, MLP_SMEM);

    k_gx1<<<T, 128>>>(x, emb, fw1_Wih, fw1_b, bw1_Wih, bw1_b);
    k_scan1<<<2, 64>>>(fw1_Whh, fw1_h0, fw1_c0, bw1_Whh, bw1_h0, bw1_c0);
    k_gx2<<<dim3(GX2_BLOCKS, 2), 256>>>(fw2_Wih, fw2_b, bw2_Wih, bw2_b);
    k_scan2<<<2, 128>>>(fw2_Whh, fw2_h0, fw2_c0, bw2_Whh, bw2_h0, bw2_c0);
    k_mlp<<<148, 320, MLP_SMEM>>>(lin1_W, lin1_b, lin2_W, lin2_b, (float*)d_out);
}